// round 14
// baseline (speedup 1.0000x reference)
#include <cuda_runtime.h>
#include <math.h>

#define NB 64
#define NP 196
#define NE 2048
#define ND 512
#define NA 512
#define NEMB 512
#define NV 10000
#define NL 52
#define NT 51
#define NX 2560
#define NBLK 148

#define OUT_PRED   0
#define OUT_CAPS   32640000
#define OUT_DECLEN 32643328
#define OUT_ALPHA  32643392
#define OUT_ORDER  33283136

typedef unsigned long long ull;

// ---- scratch ----
__device__ int   g_order[NB];
__device__ int   g_declen[NB];
__device__ float g_att1[(size_t)NB * NP * NA];
__device__ float g_h[2][NB * ND];
__device__ float g_c[NB * ND];
__device__ float g_att2p[2][NB * NA];
__device__ float g_gatep[2][NB * NE];
__device__ float g_alpha[NB * NP];
__device__ float g_awe[NB * NE];
__device__ float g_embT[NT][NB][NEMB];
__device__ float g_embg[NT][NB * 4 * ND];
__device__ float g_gawe[8][NB * 4 * ND];
__device__ float g_mean[NB * NE];
__device__ float g_initp[4][NB * 1024];

// ---- barrier / ticket state ----
__device__ unsigned g_cnt;
__device__ volatile unsigned g_gen;
__device__ unsigned g_icnt;
__device__ unsigned g_ticket;

__device__ __forceinline__ float sigf(float x) { return 1.f / (1.f + expf(-x)); }

__device__ __forceinline__ ull pack2(float x, float y) {
    ull d; asm("mov.b64 %0, {%1, %2};" : "=l"(d) : "f"(x), "f"(y)); return d;
}
__device__ __forceinline__ void fma2(ull& d, ull a, ull b) {
    asm("fma.rn.f32x2 %0, %1, %2, %0;" : "+l"(d) : "l"(a), "l"(b));
}
__device__ __forceinline__ void unpack2(ull v, float& lo, float& hi) {
    asm("mov.b64 {%0, %1}, %2;" : "=f"(lo), "=f"(hi) : "l"(v));
}
__device__ __forceinline__ void cpa4(void* dst, const void* src) {
    unsigned sd = (unsigned)__cvta_generic_to_shared(dst);
    asm volatile("cp.async.ca.shared.global [%0], [%1], 4;" :: "r"(sd), "l"(src));
}
#define CP_COMMIT asm volatile("cp.async.commit_group;")
#define CP_WAIT1  asm volatile("cp.async.wait_group 1;")
#define CP_WAIT0  asm volatile("cp.async.wait_group 0;")

// tight-spin grid barrier
__device__ __forceinline__ void gridbar(unsigned& gen) {
    __threadfence();
    __syncthreads();
    if (threadIdx.x == 0) {
        if (atomicAdd(&g_cnt, 1u) == NBLK - 1) {
            atomicExch(&g_cnt, 0u);
            __threadfence();
            g_gen = gen + 1;
        } else {
            while (g_gen == gen) { }
        }
    }
    __syncthreads();
    gen++;
}

// ===============================================================
// 512-thread 64b x 128j micro-kernel (thread = 8 rows x 2 cols)
// ===============================================================
#define XS_ST 2176   // 32*68
#define WS_ST 4224   // 32*132
__device__ __forceinline__ void compute128(const float* Xs, const float* Ws, int tid,
                                           ull aA[4], ull aB[4]) {
    const int tx = tid & 63, ty = tid >> 6;
#pragma unroll
    for (int kk = 0; kk < 32; kk++) {
        const float4 xa = *(const float4*)(Xs + kk * 68 + ty * 8);
        const float4 xb = *(const float4*)(Xs + kk * 68 + ty * 8 + 4);
        const float w0 = Ws[kk * 132 + tx];
        const float w1 = Ws[kk * 132 + 64 + tx];
        ull W0 = pack2(w0, w0), W1 = pack2(w1, w1);
        ull a0 = ((const ull*)&xa)[0], a1 = ((const ull*)&xa)[1];
        ull a2 = ((const ull*)&xb)[0], a3 = ((const ull*)&xb)[1];
        fma2(aA[0], a0, W0); fma2(aA[1], a1, W0); fma2(aA[2], a2, W0); fma2(aA[3], a3, W0);
        fma2(aB[0], a0, W1); fma2(aB[1], a1, W1); fma2(aB[2], a2, W1); fma2(aB[3], a3, W1);
    }
}

template<int NCH>
__device__ __forceinline__ void run_kmajor(
    const float* __restrict__ Xg, int xstride,
    const float* __restrict__ Wg, size_t wstride, int vw, int kbase,
    bool wact, ull aA[4], ull aB[4], float* Xs, float* Ws, int tid)
{
    auto stage = [&](int c, int st) {
        int k0 = kbase + (c << 5);
#pragma unroll
        for (int i = 0; i < 4; i++) {
            int idx = (i << 9) + tid;
            int k = idx & 31, b = idx >> 5;
            cpa4(&Xs[st * XS_ST + k * 68 + b], Xg + (size_t)b * xstride + k0 + k);
        }
#pragma unroll
        for (int i = 0; i < 8; i++) {
            int idx = (i << 9) + tid;
            int j = idx & 127, k = idx >> 7;
            int jc = (j < vw) ? j : 0;
            cpa4(&Ws[st * WS_ST + k * 132 + j], Wg + (size_t)(k0 + k) * wstride + jc);
        }
        CP_COMMIT;
    };
    stage(0, 0);
    for (int c = 0; c < NCH; c++) {
        int st = c & 1;
        if (c < NCH - 1) { stage(c + 1, st ^ 1); CP_WAIT1; }
        else            { CP_WAIT0; }
        __syncthreads();
        if (wact) compute128(Xs + st * XS_ST, Ws + st * WS_ST, tid, aA, aB);
        __syncthreads();
    }
}

template<int NCH>
__device__ __forceinline__ void run_mix(
    const float* __restrict__ h, const float* __restrict__ awe,
    const float* __restrict__ Whh_j0, const float* __restrict__ Wih_j0,
    int kbase, bool wact, ull aA[4], ull aB[4], float* Xs, float* Ws, int tid)
{
    auto stage = [&](int c, int st) {
        int k0 = kbase + (c << 5);
#pragma unroll
        for (int i = 0; i < 4; i++) {
            int idx = (i << 9) + tid;
            int k = idx & 31, b = idx >> 5;
            int gk = k0 + k;
            const float* src = (gk < ND) ? (h + (size_t)b * ND + gk)
                                         : (awe + (size_t)b * NE + gk - ND);
            cpa4(&Xs[st * XS_ST + k * 68 + b], src);
        }
#pragma unroll
        for (int i = 0; i < 8; i++) {
            int idx = (i << 9) + tid;
            int k = idx & 31, j = idx >> 5;
            int gk = k0 + k;
            const float* src = (gk < ND) ? (Whh_j0 + (size_t)j * ND + gk)
                                         : (Wih_j0 + (size_t)j * NX + gk);
            cpa4(&Ws[st * WS_ST + k * 132 + j], src);
        }
        CP_COMMIT;
    };
    stage(0, 0);
    for (int c = 0; c < NCH; c++) {
        int st = c & 1;
        if (c < NCH - 1) { stage(c + 1, st ^ 1); CP_WAIT1; }
        else            { CP_WAIT0; }
        __syncthreads();
        if (wact) compute128(Xs + st * XS_ST, Ws + st * WS_ST, tid, aA, aB);
        __syncthreads();
    }
}

// ===============================================================
// 256-thread 64b x 128j GEMM (prologue kernels)
// ===============================================================
template<bool KMAJOR, int NCH>
__device__ __forceinline__ void gemm_acc(
    const float* __restrict__ Xg, int xstride,
    const float* __restrict__ Wg, size_t wstride, int vw,
    bool wact, ull acc[4][4], float* Xs, float* Ws, int tid)
{
    const int tx = tid & 31, ty = tid >> 5;
    auto stage = [&](int k0, int st) {
#pragma unroll
        for (int i = 0; i < 8; i++) {
            int idx = (i << 8) + tid;
            int k = idx & 31, b = idx >> 5;
            cpa4(&Xs[st * XS_ST + k * 68 + b], Xg + (size_t)b * xstride + k0 + k);
        }
#pragma unroll
        for (int i = 0; i < 16; i++) {
            int idx = (i << 8) + tid;
            int j = KMAJOR ? (idx & 127) : (idx >> 5);
            int k = KMAJOR ? (idx >> 7) : (idx & 31);
            int jc = (j < vw) ? j : 0;
            const float* src = KMAJOR ? (Wg + (size_t)(k0 + k) * wstride + jc)
                                      : (Wg + (size_t)jc * wstride + k0 + k);
            cpa4(&Ws[st * WS_ST + k * 132 + j], src);
        }
        CP_COMMIT;
    };
    stage(0, 0);
    for (int c = 0; c < NCH; c++) {
        int st = c & 1;
        if (c < NCH - 1) { stage((c + 1) << 5, st ^ 1); CP_WAIT1; }
        else            { CP_WAIT0; }
        __syncthreads();
        if (wact) {
#pragma unroll
            for (int kk = 0; kk < 32; kk++) {
                const float4 xa = *(const float4*)(Xs + st * XS_ST + kk * 68 + ty * 8);
                const float4 xb = *(const float4*)(Xs + st * XS_ST + kk * 68 + ty * 8 + 4);
                const float4 wv = *(const float4*)(Ws + st * WS_ST + kk * 132 + tx * 4);
                ull a0 = ((const ull*)&xa)[0], a1 = ((const ull*)&xa)[1];
                ull a2 = ((const ull*)&xb)[0], a3 = ((const ull*)&xb)[1];
                ull w0 = pack2(wv.x, wv.x), w1 = pack2(wv.y, wv.y);
                ull w2 = pack2(wv.z, wv.z), w3 = pack2(wv.w, wv.w);
                fma2(acc[0][0], a0, w0); fma2(acc[0][1], a0, w1);
                fma2(acc[0][2], a0, w2); fma2(acc[0][3], a0, w3);
                fma2(acc[1][0], a1, w0); fma2(acc[1][1], a1, w1);
                fma2(acc[1][2], a1, w2); fma2(acc[1][3], a1, w3);
                fma2(acc[2][0], a2, w0); fma2(acc[2][1], a2, w1);
                fma2(acc[2][2], a2, w2); fma2(acc[2][3], a2, w3);
                fma2(acc[3][0], a3, w0); fma2(acc[3][1], a3, w1);
                fma2(acc[3][2], a3, w2); fma2(acc[3][3], a3, w3);
            }
        }
        __syncthreads();
    }
}

// ---------------------------------------------------------------
__global__ void k_sort(const int* __restrict__ clen, const int* __restrict__ caps,
                       float* __restrict__ out) {
    int i = threadIdx.x;
    __shared__ int len[NB];
    if (i < NB) len[i] = clen[i];
    __syncthreads();
    if (i < NB) {
        int li = len[i], r = 0;
        for (int j = 0; j < NB; j++) {
            int lj = len[j];
            if (lj > li || (lj == li && j < i)) r++;
        }
        g_order[r] = i;
    }
    __syncthreads();
    if (i < NB) {
        int src = g_order[i];
        int dl = len[src] - 1;
        g_declen[i] = dl;
        out[OUT_DECLEN + i] = (float)dl;
        out[OUT_ORDER + i] = (float)src;
        for (int t = 0; t < NL; t++)
            out[OUT_CAPS + i * NL + t] = (float)caps[src * NL + t];
    }
}

__global__ void k_prep(const int* __restrict__ caps, const float* __restrict__ embW,
                       const float* __restrict__ enc) {
    const int bx = blockIdx.x, tid = threadIdx.x;
    if (bx < 512) {
        int b = bx >> 3;
        int e = (bx & 7) * 256 + tid;
        const float* base = enc + (size_t)g_order[b] * NP * NE + e;
        float s = 0.f;
#pragma unroll 7
        for (int p = 0; p < NP; p++) s += base[(size_t)p * NE];
        g_mean[b * NE + e] = s * (1.0f / NP);
    } else {
        int idx = bx - 512;
        int tt = idx >> 6, b = idx & 63;
        int cap = caps[g_order[b] * NL + tt];
        for (int i = tid; i < NEMB; i += 256)
            g_embT[tt][b][i] = embW[(size_t)cap * NEMB + i];
    }
}

__global__ __launch_bounds__(256) void k_embg(const float* __restrict__ Wih,
                                              const float* __restrict__ bih,
                                              const float* __restrict__ bhh) {
    extern __shared__ float dyn[];
    float* Xs = dyn;
    float* Ws = dyn + 2 * XS_ST;
    const int tid = threadIdx.x, tx = tid & 31, ty = tid >> 5;
    const int t = blockIdx.x >> 4;
    const int j0 = (blockIdx.x & 15) * 128;
    ull acc[4][4] = {};
    gemm_acc<false, 16>(&g_embT[t][0][0], NEMB, Wih + (size_t)j0 * NX, NX, 128,
                        true, acc, Xs, Ws, tid);
#pragma unroll
    for (int p = 0; p < 4; p++) {
        int b0r = ty * 8 + 2 * p;
        const float4 b1 = *(const float4*)&bih[j0 + tx * 4];
        const float4 b2 = *(const float4*)&bhh[j0 + tx * 4];
        float4 lov, hiv;
        unpack2(acc[p][0], lov.x, hiv.x); unpack2(acc[p][1], lov.y, hiv.y);
        unpack2(acc[p][2], lov.z, hiv.z); unpack2(acc[p][3], lov.w, hiv.w);
        lov.x += b1.x + b2.x; lov.y += b1.y + b2.y; lov.z += b1.z + b2.z; lov.w += b1.w + b2.w;
        hiv.x += b1.x + b2.x; hiv.y += b1.y + b2.y; hiv.z += b1.z + b2.z; hiv.w += b1.w + b2.w;
        *(float4*)&g_embg[t][b0r * (4 * ND) + j0 + tx * 4] = lov;
        *(float4*)&g_embg[t][(b0r + 1) * (4 * ND) + j0 + tx * 4] = hiv;
    }
}

__global__ __launch_bounds__(256) void k_init(const float* __restrict__ HW,
                                              const float* __restrict__ CW,
                                              const float* __restrict__ Hb,
                                              const float* __restrict__ Cb) {
    extern __shared__ float dyn[];
    __shared__ int lastf;
    float* Xs = dyn;
    float* Ws = dyn + 2 * XS_ST;
    const int tid = threadIdx.x, tx = tid & 31, ty = tid >> 5;
    const int j0 = (blockIdx.x & 7) * 128, ks = blockIdx.x >> 3;
    const float* W = (j0 < 512) ? (HW + j0) : (CW + j0 - 512);
    ull acc[4][4] = {};
    gemm_acc<true, 16>(g_mean + ks * 512, NE, W + (size_t)ks * 512 * ND, ND, 128,
                       true, acc, Xs, Ws, tid);
#pragma unroll
    for (int p = 0; p < 4; p++) {
        int b0r = ty * 8 + 2 * p;
        float4 lov, hiv;
        unpack2(acc[p][0], lov.x, hiv.x); unpack2(acc[p][1], lov.y, hiv.y);
        unpack2(acc[p][2], lov.z, hiv.z); unpack2(acc[p][3], lov.w, hiv.w);
        *(float4*)&g_initp[ks][b0r * 1024 + j0 + tx * 4] = lov;
        *(float4*)&g_initp[ks][(b0r + 1) * 1024 + j0 + tx * 4] = hiv;
    }
    __threadfence();
    __syncthreads();
    if (tid == 0) lastf = (atomicAdd(&g_icnt, 1u) == 31);
    __syncthreads();
    if (lastf) {
        __threadfence();
        for (int i = tid; i < NB * 1024; i += 256) {
            int b = i >> 10, j = i & 1023;
            float s = g_initp[0][i] + g_initp[1][i] + g_initp[2][i] + g_initp[3][i];
            if (j < 512) g_h[0][b * ND + j] = s + Hb[j];
            else         g_c[b * ND + j - 512] = s + Cb[j - 512];
        }
        if (tid == 0) atomicExch(&g_icnt, 0u);
    }
}

#define AXS_ST 4224
__global__ __launch_bounds__(256) void k_att1(const float* __restrict__ enc,
                                              const float* __restrict__ W,
                                              const float* __restrict__ bias) {
    extern __shared__ float dyn[];
    float* Xs = dyn;
    float* Ws = dyn + 2 * AXS_ST;
    __shared__ int rowBase[128];
    const int bn = blockIdx.x, bm = blockIdx.y, tid = threadIdx.x;
    const int row0 = bm * 128;
    if (tid < 128) {
        int m = row0 + tid;
        rowBase[tid] = g_order[m / NP] * NP + (m % NP);
    }
    __syncthreads();
    const int tx = tid & 31, ty = tid >> 5;
    ull acc[8][4] = {};
    auto stage = [&](int k0, int st) {
#pragma unroll
        for (int i = 0; i < 16; i++) {
            int idx = (i << 8) + tid;
            int k = idx & 31, m = idx >> 5;
            cpa4(&Xs[st * AXS_ST + k * 132 + m], enc + (size_t)rowBase[m] * NE + k0 + k);
        }
#pragma unroll
        for (int i = 0; i < 16; i++) {
            int idx = (i << 8) + tid;
            int j = idx & 127, k = idx >> 7;
            cpa4(&Ws[st * AXS_ST + k * 132 + j], W + (size_t)(k0 + k) * NA + bn * 128 + j);
        }
        CP_COMMIT;
    };
    stage(0, 0);
    for (int c = 0; c < 64; c++) {
        int st = c & 1;
        if (c < 63) { stage((c + 1) << 5, st ^ 1); CP_WAIT1; }
        else        { CP_WAIT0; }
        __syncthreads();
#pragma unroll
        for (int kk = 0; kk < 32; kk++) {
            const float* xrow = Xs + st * AXS_ST + kk * 132 + ty * 16;
            const float4 x0 = *(const float4*)(xrow);
            const float4 x1 = *(const float4*)(xrow + 4);
            const float4 x2 = *(const float4*)(xrow + 8);
            const float4 x3 = *(const float4*)(xrow + 12);
            const float4 wv = *(const float4*)(Ws + st * AXS_ST + kk * 132 + tx * 4);
            ull a[8];
            a[0] = ((const ull*)&x0)[0]; a[1] = ((const ull*)&x0)[1];
            a[2] = ((const ull*)&x1)[0]; a[3] = ((const ull*)&x1)[1];
            a[4] = ((const ull*)&x2)[0]; a[5] = ((const ull*)&x2)[1];
            a[6] = ((const ull*)&x3)[0]; a[7] = ((const ull*)&x3)[1];
            ull w0 = pack2(wv.x, wv.x), w1 = pack2(wv.y, wv.y);
            ull w2 = pack2(wv.z, wv.z), w3 = pack2(wv.w, wv.w);
#pragma unroll
            for (int p = 0; p < 8; p++) {
                fma2(acc[p][0], a[p], w0); fma2(acc[p][1], a[p], w1);
                fma2(acc[p][2], a[p], w2); fma2(acc[p][3], a[p], w3);
            }
        }
        __syncthreads();
    }
    const float4 bv = *(const float4*)&bias[bn * 128 + tx * 4];
#pragma unroll
    for (int p = 0; p < 8; p++) {
        float4 lov, hiv;
        unpack2(acc[p][0], lov.x, hiv.x); unpack2(acc[p][1], lov.y, hiv.y);
        unpack2(acc[p][2], lov.z, hiv.z); unpack2(acc[p][3], lov.w, hiv.w);
        lov.x += bv.x; lov.y += bv.y; lov.z += bv.z; lov.w += bv.w;
        hiv.x += bv.x; hiv.y += bv.y; hiv.z += bv.z; hiv.w += bv.w;
        size_t m0 = row0 + ty * 16 + 2 * p;
        *(float4*)&g_att1[m0 * NA + bn * 128 + tx * 4] = lov;
        *(float4*)&g_att1[(m0 + 1) * NA + bn * 128 + tx * 4] = hiv;
    }
}

// ---------------------------------------------------------------
// alpha softmax only (512 threads, one block per b)
// ---------------------------------------------------------------
__device__ void alpha_only(int b, int t, const float* __restrict__ fullw,
                           const float* __restrict__ fullb,
                           float* __restrict__ out, const int* sD) {
    __shared__ float att2s[NA];
    __shared__ float ws[NA];
    __shared__ float ev[NP];
    __shared__ float red[16];
    __shared__ float smax, ssum;
    const int tid = threadIdx.x, warp = tid >> 5, lane = tid & 31;
    float* aout = out + OUT_ALPHA + ((size_t)b * NT + t) * NP;
    if (t >= sD[b]) {
        if (tid < NP) aout[tid] = 0.f;
        return;
    }
    att2s[tid] = g_att2p[0][b * NA + tid] + g_att2p[1][b * NA + tid];
    ws[tid] = fullw[tid];
    __syncthreads();
    const float fb = fullb[0];
    for (int p = warp; p < NP; p += 16) {
        const float* a1 = g_att1 + ((size_t)(b * NP + p)) * NA;
        float s = 0.f;
#pragma unroll 4
        for (int a = lane; a < NA; a += 32) {
            float v = a1[a] + att2s[a];
            s += fmaxf(v, 0.f) * ws[a];
        }
#pragma unroll
        for (int o = 16; o; o >>= 1) s += __shfl_xor_sync(0xffffffffu, s, o);
        if (lane == 0) ev[p] = s + fb;
    }
    __syncthreads();
    float v = (tid < NP) ? ev[tid] : -3.0e38f;
    float m = v;
#pragma unroll
    for (int o = 16; o; o >>= 1) m = fmaxf(m, __shfl_xor_sync(0xffffffffu, m, o));
    if (lane == 0) red[warp] = m;
    __syncthreads();
    if (tid == 0) { float mm = red[0]; for (int i = 1; i < 16; i++) mm = fmaxf(mm, red[i]); smax = mm; }
    __syncthreads();
    float ex = (tid < NP) ? expf(v - smax) : 0.f;
    float s2 = ex;
#pragma unroll
    for (int o = 16; o; o >>= 1) s2 += __shfl_xor_sync(0xffffffffu, s2, o);
    if (lane == 0) red[warp] = s2;
    __syncthreads();
    if (tid == 0) { float ss = 0.f; for (int i = 0; i < 16; i++) ss += red[i]; ssum = ss; }
    __syncthreads();
    if (tid < NP) {
        float a = ex / ssum;
        g_alpha[b * NP + tid] = a;
        aout[tid] = a;
    }
}

// awe tile: (b, ec) — e slice of 512; gate-combine fused
__device__ void awe_tile(int b, int ec, const float* __restrict__ enc, const int* sO) {
    __shared__ float al[NP];
    const int tid = threadIdx.x;
    if (tid < NP) al[tid] = g_alpha[b * NP + tid];
    __syncthreads();
    const int e = ec * 512 + tid;
    const float* eb = enc + (size_t)sO[b] * NP * NE + e;
    float a0 = 0.f, a1 = 0.f, a2 = 0.f, a3 = 0.f;
#pragma unroll 4
    for (int p = 0; p < NP; p += 4) {
        a0 += al[p]     * eb[(size_t)p * NE];
        a1 += al[p + 1] * eb[(size_t)(p + 1) * NE];
        a2 += al[p + 2] * eb[(size_t)(p + 2) * NE];
        a3 += al[p + 3] * eb[(size_t)(p + 3) * NE];
    }
    float aw = (a0 + a1) + (a2 + a3);
    float gp = g_gatep[0][b * NE + e] + g_gatep[1][b * NE + e];
    g_awe[b * NE + e] = aw * sigf(gp);
    __syncthreads();   // protect al before next claim overwrites
}

// ---------------------------------------------------------------
// Persistent loop: 148 blocks x 512 threads, 5 windows per step.
// ---------------------------------------------------------------
__global__ __launch_bounds__(512) void k_loop(
        const float* __restrict__ enc,
        const float* __restrict__ attW, const float* __restrict__ attb,
        const float* __restrict__ fbW,  const float* __restrict__ fbb,
        const float* __restrict__ fullw, const float* __restrict__ fullb,
        const float* __restrict__ Wih,  const float* __restrict__ Whh,
        const float* __restrict__ fcW,  const float* __restrict__ fcb,
        float* __restrict__ out) {
    extern __shared__ float dyn[];
    float* Xs = dyn;
    float* Ws = dyn + 2 * XS_ST;
    __shared__ int sD[NB], sO[NB];
    __shared__ int stk;
    const int bid = blockIdx.x, tid = threadIdx.x;
    const int tx = tid & 63, ty = tid >> 6;
    unsigned gen = g_gen;
    if (tid < NB) { sD[tid] = g_declen[tid]; sO[tid] = g_order[tid]; }
    __syncthreads();

    for (int t = 0; t <= NT; t++) {
        const float* h = g_h[t & 1];
        const bool wact = (t < sD[ty * 8]);
        ull fA[4] = {}, fB[4] = {};
        const bool isfc = (bid >= 40 && bid < 119);
        const int fj0 = (bid - 40) * 128;
        const int fvw = (NV - fj0 > 128) ? 128 : (NV - fj0);
        const bool fcact = isfc && (t >= 1);
        const bool fwact = (t - 1 < sD[ty * 8]);

        // ---------------- W1: att2 + gate + fc part1 ----------------
        if (t < NT && bid < 8) {
            int jt = bid >> 1, ks = bid & 1, j0 = jt * 128;
            ull aA[4] = {}, aB[4] = {};
            run_kmajor<8>(h, ND, attW + j0, NA, 128, ks * 256, wact, aA, aB, Xs, Ws, tid);
            if (wact) {
                float bvA = (ks == 0) ? attb[j0 + tx] : 0.f;
                float bvB = (ks == 0) ? attb[j0 + 64 + tx] : 0.f;
#pragma unroll
                for (int p = 0; p < 4; p++) {
                    int bA = ty * 8 + 2 * p;
                    float lo, hi;
                    unpack2(aA[p], lo, hi);
                    g_att2p[ks][bA * NA + j0 + tx] = lo + bvA;
                    g_att2p[ks][(bA + 1) * NA + j0 + tx] = hi + bvA;
                    unpack2(aB[p], lo, hi);
                    g_att2p[ks][bA * NA + j0 + 64 + tx] = lo + bvB;
                    g_att2p[ks][(bA + 1) * NA + j0 + 64 + tx] = hi + bvB;
                }
            }
        } else if (t < NT && bid < 40) {
            int idx = bid - 8;
            int jt = idx >> 1, ks = idx & 1, j0 = jt * 128;
            ull aA[4] = {}, aB[4] = {};
            run_kmajor<8>(h, ND, fbW + j0, NE, 128, ks * 256, wact, aA, aB, Xs, Ws, tid);
            if (wact) {
                float bvA = (ks == 0) ? fbb[j0 + tx] : 0.f;
                float bvB = (ks == 0) ? fbb[j0 + 64 + tx] : 0.f;
#pragma unroll
                for (int p = 0; p < 4; p++) {
                    int bA = ty * 8 + 2 * p;
                    float lo, hi;
                    unpack2(aA[p], lo, hi);
                    g_gatep[ks][bA * NE + j0 + tx] = lo + bvA;
                    g_gatep[ks][(bA + 1) * NE + j0 + tx] = hi + bvA;
                    unpack2(aB[p], lo, hi);
                    g_gatep[ks][bA * NE + j0 + 64 + tx] = lo + bvB;
                    g_gatep[ks][(bA + 1) * NE + j0 + 64 + tx] = hi + bvB;
                }
            }
        } else if (fcact) {
            run_kmajor<8>(h, ND, fcW + fj0, NV, fvw, 0, fwact, fA, fB, Xs, Ws, tid);
        }
        gridbar(gen);

        // ---------------- W2: fc part2 + writeout | alpha ----------------
        if (fcact) {
            run_kmajor<8>(h, ND, fcW + fj0, NV, fvw, 256, fwact, fA, fB, Xs, Ws, tid);
            int tprev = t - 1;
#pragma unroll
            for (int p = 0; p < 4; p++) {
                int bA = ty * 8 + 2 * p, bB = bA + 1;
                bool actA = tprev < sD[bA];
                bool actB = tprev < sD[bB];
                int cA = fj0 + tx, cB = fj0 + 64 + tx;
                float lo, hi;
                if (cA < NV) {
                    float bv = fcb[cA];
                    unpack2(fA[p], lo, hi);
                    out[OUT_PRED + (size_t)(bA * NT + tprev) * NV + cA] = actA ? lo + bv : 0.f;
                    out[OUT_PRED + (size_t)(bB * NT + tprev) * NV + cA] = actB ? hi + bv : 0.f;
                }
                if (cB < NV) {
                    float bv = fcb[cB];
                    unpack2(fB[p], lo, hi);
                    out[OUT_PRED + (size_t)(bA * NT + tprev) * NV + cB] = actA ? lo + bv : 0.f;
                    out[OUT_PRED + (size_t)(bB * NT + tprev) * NV + cB] = actB ? hi + bv : 0.f;
                }
            }
        } else if (t < NT) {
            int ab = (bid < 40) ? bid : ((bid >= 119 && bid < 143) ? bid - 79 : -1);
            if (ab >= 0) alpha_only(ab, t, fullw, fullb, out, sD);
            if (bid == 147 && tid == 0) atomicExch(&g_ticket, 0u);
        }
        if (t == NT) break;
        gridbar(gen);

        // ---------------- W2b: awe — dynamic tickets over 256 tiles ----------------
        while (true) {
            __syncthreads();
            if (tid == 0) stk = (int)atomicAdd(&g_ticket, 1u);
            __syncthreads();
            int tk = stk;
            if (tk >= 256) break;
            int b = tk >> 2;
            if (t >= sD[b]) continue;
            awe_tile(b, tk & 3, enc, sO);
        }
        gridbar(gen);

        // ---------------- W3: merged [h;awe] gates ----------------
        if (bid < 128) {
            int jt = bid & 15, ks = bid >> 4;
            int j0 = jt * 128;
            ull aA[4] = {}, aB[4] = {};
            run_mix<10>(h, g_awe, Whh + (size_t)j0 * ND, Wih + (size_t)j0 * NX,
                        ks * 320, wact, aA, aB, Xs, Ws, tid);
            if (wact) {
#pragma unroll
                for (int p = 0; p < 4; p++) {
                    int bA = ty * 8 + 2 * p;
                    float lo, hi;
                    unpack2(aA[p], lo, hi);
                    g_gawe[ks][bA * (4 * ND) + j0 + tx] = lo;
                    g_gawe[ks][(bA + 1) * (4 * ND) + j0 + tx] = hi;
                    unpack2(aB[p], lo, hi);
                    g_gawe[ks][bA * (4 * ND) + j0 + 64 + tx] = lo;
                    g_gawe[ks][(bA + 1) * (4 * ND) + j0 + 64 + tx] = hi;
                }
            }
        }
        gridbar(gen);

        // ---------------- W4: lstm ----------------
        if (bid < NB && t < sD[bid]) {
            const int b = bid, d = tid;
            float gv[4];
#pragma unroll
            for (int q = 0; q < 4; q++) {
                int j = q * ND + d;
                float s = g_embg[t][b * (4 * ND) + j];
#pragma unroll
                for (int ks = 0; ks < 8; ks++) s += g_gawe[ks][b * (4 * ND) + j];
                gv[q] = s;
            }
            float i_ = sigf(gv[0]);
            float f_ = sigf(gv[1]);
            float gg = tanhf(gv[2]);
            float o_ = sigf(gv[3]);
            float c = f_ * g_c[b * ND + d] + i_ * gg;
            g_c[b * ND + d] = c;
            g_h[(t & 1) ^ 1][b * ND + d] = o_ * tanhf(c);
        }
        gridbar(gen);
    }
}

// ---------------------------------------------------------------
extern "C" void kernel_launch(void* const* d_in, const int* in_sizes, int n_in,
                              void* d_out, int out_size) {
    (void)in_sizes; (void)n_in; (void)out_size;
    const float* enc     = (const float*)d_in[0];
    const int*   caps    = (const int*)d_in[1];
    const int*   clen    = (const int*)d_in[2];
    const float* embW    = (const float*)d_in[3];
    const float* attEncW = (const float*)d_in[4];
    const float* attEncB = (const float*)d_in[5];
    const float* attDecW = (const float*)d_in[6];
    const float* attDecB = (const float*)d_in[7];
    const float* fullW   = (const float*)d_in[8];
    const float* fullB   = (const float*)d_in[9];
    const float* Wih     = (const float*)d_in[10];
    const float* Whh     = (const float*)d_in[11];
    const float* bih     = (const float*)d_in[12];
    const float* bhh     = (const float*)d_in[13];
    const float* iHW     = (const float*)d_in[14];
    const float* iHb     = (const float*)d_in[15];
    const float* iCW     = (const float*)d_in[16];
    const float* iCb     = (const float*)d_in[17];
    const float* fbW     = (const float*)d_in[18];
    const float* fbb     = (const float*)d_in[19];
    const float* fcW     = (const float*)d_in[20];
    const float* fcb     = (const float*)d_in[21];
    float* out = (float*)d_out;

    const int SM_G128 = (2 * XS_ST + 2 * WS_ST) * 4;   // 51200
    const int SM_ATT1 = (4 * AXS_ST) * 4;              // 67584
    static int configured = 0;
    if (!configured) {
        cudaFuncSetAttribute(k_init, cudaFuncAttributeMaxDynamicSharedMemorySize, SM_G128);
        cudaFuncSetAttribute(k_embg, cudaFuncAttributeMaxDynamicSharedMemorySize, SM_G128);
        cudaFuncSetAttribute(k_att1, cudaFuncAttributeMaxDynamicSharedMemorySize, SM_ATT1);
        cudaFuncSetAttribute(k_loop, cudaFuncAttributeMaxDynamicSharedMemorySize, SM_G128);
        configured = 1;
    }

    k_sort<<<1, 64>>>(clen, caps, out);
    k_prep<<<512 + NT * NB, 256>>>(caps, embW, enc);
    k_init<<<32, 256, SM_G128>>>(iHW, iCW, iHb, iCb);
    k_embg<<<NT * 16, 256, SM_G128>>>(Wih, bih, bhh);
    k_att1<<<dim3(4, 98), 256, SM_ATT1>>>(enc, attEncW, attEncB);
    k_loop<<<NBLK, 512, SM_G128>>>(enc, attDecW, attDecB, fbW, fbb,
                                   fullW, fullB, Wih, Whh, fcW, fcb, out);
}

// round 16
// speedup vs baseline: 1.0424x; 1.0424x over previous
#include <cuda_runtime.h>
#include <math.h>

#define NB 64
#define NP 196
#define NE 2048
#define ND 512
#define NA 512
#define NEMB 512
#define NV 10000
#define NL 52
#define NT 51
#define NX 2560
#define NBLK 148

#define OUT_PRED   0
#define OUT_CAPS   32640000
#define OUT_DECLEN 32643328
#define OUT_ALPHA  32643392
#define OUT_ORDER  33283136

typedef unsigned long long ull;

__device__ int   g_order[NB];
__device__ int   g_declen[NB];
__device__ float g_att1[(size_t)NB * NP * NA];
__device__ float g_h[2][NB * ND];
__device__ float g_c[NB * ND];
__device__ float g_att2p[2][NB * NA];
__device__ float g_gatep[2][NB * NE];
__device__ float g_awe[NB * NE];
__device__ float g_embT[NT][NB][NEMB];
__device__ float g_embg[NT][NB * 4 * ND];
__device__ float g_gawe[8][NB * 4 * ND];
__device__ float g_mean[NB * NE];
__device__ float g_initp[4][NB * 1024];

__device__ unsigned g_cnt;
__device__ volatile unsigned g_gen;
__device__ unsigned g_icnt;
__device__ unsigned g_ptick;

__device__ __forceinline__ float sigf(float x) { return 1.f / (1.f + expf(-x)); }
__device__ __forceinline__ ull pack2(float x, float y) {
    ull d; asm("mov.b64 %0, {%1, %2};" : "=l"(d) : "f"(x), "f"(y)); return d;
}
__device__ __forceinline__ void fma2(ull& d, ull a, ull b) {
    asm("fma.rn.f32x2 %0, %1, %2, %0;" : "+l"(d) : "l"(a), "l"(b));
}
__device__ __forceinline__ void unpack2(ull v, float& lo, float& hi) {
    asm("mov.b64 {%0, %1}, %2;" : "=f"(lo), "=f"(hi) : "l"(v));
}
__device__ __forceinline__ void cpa4(void* dst, const void* src) {
    unsigned sd = (unsigned)__cvta_generic_to_shared(dst);
    asm volatile("cp.async.ca.shared.global [%0], [%1], 4;" :: "r"(sd), "l"(src));
}
#define CP_COMMIT asm volatile("cp.async.commit_group;")
#define CP_WAIT1  asm volatile("cp.async.wait_group 1;")
#define CP_WAIT0  asm volatile("cp.async.wait_group 0;")

__device__ __forceinline__ void gridbar(unsigned& gen) {
    __threadfence();
    __syncthreads();
    if (threadIdx.x == 0) {
        if (atomicAdd(&g_cnt, 1u) == NBLK - 1) {
            atomicExch(&g_cnt, 0u);
            __threadfence();
            g_gen = gen + 1;
        } else {
            while (g_gen == gen) { }
        }
    }
    __syncthreads();
    gen++;
}

// ==== 512-thread 64b x 128j micro-kernel (loop) ====
#define XS_ST 2176
#define WS_ST 4224
__device__ __forceinline__ void compute128(const float* Xs, const float* Ws, int tid,
                                           ull aA[4], ull aB[4]) {
    const int tx = tid & 63, ty = tid >> 6;
#pragma unroll
    for (int kk = 0; kk < 32; kk++) {
        const float4 xa = *(const float4*)(Xs + kk * 68 + ty * 8);
        const float4 xb = *(const float4*)(Xs + kk * 68 + ty * 8 + 4);
        const float w0 = Ws[kk * 132 + tx];
        const float w1 = Ws[kk * 132 + 64 + tx];
        ull W0 = pack2(w0, w0), W1 = pack2(w1, w1);
        ull a0 = ((const ull*)&xa)[0], a1 = ((const ull*)&xa)[1];
        ull a2 = ((const ull*)&xb)[0], a3 = ((const ull*)&xb)[1];
        fma2(aA[0], a0, W0); fma2(aA[1], a1, W0); fma2(aA[2], a2, W0); fma2(aA[3], a3, W0);
        fma2(aB[0], a0, W1); fma2(aB[1], a1, W1); fma2(aB[2], a2, W1); fma2(aB[3], a3, W1);
    }
}

template<int NCH>
__device__ __forceinline__ void run_kmajor(
    const float* __restrict__ Xg, int xstride,
    const float* __restrict__ Wg, size_t wstride, int vw, int kbase,
    bool wact, ull aA[4], ull aB[4], float* Xs, float* Ws, int tid)
{
    auto stage = [&](int c, int st) {
        int k0 = kbase + (c << 5);
#pragma unroll
        for (int i = 0; i < 4; i++) {
            int idx = (i << 9) + tid;
            int k = idx & 31, b = idx >> 5;
            cpa4(&Xs[st * XS_ST + k * 68 + b], Xg + (size_t)b * xstride + k0 + k);
        }
#pragma unroll
        for (int i = 0; i < 8; i++) {
            int idx = (i << 9) + tid;
            int j = idx & 127, k = idx >> 7;
            int jc = (j < vw) ? j : 0;
            cpa4(&Ws[st * WS_ST + k * 132 + j], Wg + (size_t)(k0 + k) * wstride + jc);
        }
        CP_COMMIT;
    };
    stage(0, 0);
    for (int c = 0; c < NCH; c++) {
        int st = c & 1;
        if (c < NCH - 1) { stage(c + 1, st ^ 1); CP_WAIT1; }
        else            { CP_WAIT0; }
        __syncthreads();
        if (wact) compute128(Xs + st * XS_ST, Ws + st * WS_ST, tid, aA, aB);
        __syncthreads();
    }
}

template<int NCH>
__device__ __forceinline__ void run_mix(
    const float* __restrict__ h, const float* __restrict__ awe,
    const float* __restrict__ Whh_j0, const float* __restrict__ Wih_j0,
    int kbase, bool wact, ull aA[4], ull aB[4], float* Xs, float* Ws, int tid)
{
    auto stage = [&](int c, int st) {
        int k0 = kbase + (c << 5);
#pragma unroll
        for (int i = 0; i < 4; i++) {
            int idx = (i << 9) + tid;
            int k = idx & 31, b = idx >> 5;
            int gk = k0 + k;
            const float* src = (gk < ND) ? (h + (size_t)b * ND + gk)
                                         : (awe + (size_t)b * NE + gk - ND);
            cpa4(&Xs[st * XS_ST + k * 68 + b], src);
        }
#pragma unroll
        for (int i = 0; i < 8; i++) {
            int idx = (i << 9) + tid;
            int k = idx & 31, j = idx >> 5;
            int gk = k0 + k;
            const float* src = (gk < ND) ? (Whh_j0 + (size_t)j * ND + gk)
                                         : (Wih_j0 + (size_t)j * NX + gk);
            cpa4(&Ws[st * WS_ST + k * 132 + j], src);
        }
        CP_COMMIT;
    };
    stage(0, 0);
    for (int c = 0; c < NCH; c++) {
        int st = c & 1;
        if (c < NCH - 1) { stage(c + 1, st ^ 1); CP_WAIT1; }
        else            { CP_WAIT0; }
        __syncthreads();
        if (wact) compute128(Xs + st * XS_ST, Ws + st * WS_ST, tid, aA, aB);
        __syncthreads();
    }
}

// ==== 256-thread 64b x 128j GEMM (prologue tiles) ====
template<bool KMAJOR, int NCH>
__device__ __forceinline__ void gemm_acc(
    const float* __restrict__ Xg, int xstride,
    const float* __restrict__ Wg, size_t wstride, int vw,
    ull acc[4][4], float* Xs, float* Ws, int tid)
{
    const int tx = tid & 31, ty = tid >> 5;
    auto stage = [&](int k0, int st) {
#pragma unroll
        for (int i = 0; i < 8; i++) {
            int idx = (i << 8) + tid;
            int k = idx & 31, b = idx >> 5;
            cpa4(&Xs[st * XS_ST + k * 68 + b], Xg + (size_t)b * xstride + k0 + k);
        }
#pragma unroll
        for (int i = 0; i < 16; i++) {
            int idx = (i << 8) + tid;
            int j = KMAJOR ? (idx & 127) : (idx >> 5);
            int k = KMAJOR ? (idx >> 7) : (idx & 31);
            int jc = (j < vw) ? j : 0;
            const float* src = KMAJOR ? (Wg + (size_t)(k0 + k) * wstride + jc)
                                      : (Wg + (size_t)jc * wstride + k0 + k);
            cpa4(&Ws[st * WS_ST + k * 132 + j], src);
        }
        CP_COMMIT;
    };
    stage(0, 0);
    for (int c = 0; c < NCH; c++) {
        int st = c & 1;
        if (c < NCH - 1) { stage((c + 1) << 5, st ^ 1); CP_WAIT1; }
        else            { CP_WAIT0; }
        __syncthreads();
#pragma unroll
        for (int kk = 0; kk < 32; kk++) {
            const float4 xa = *(const float4*)(Xs + st * XS_ST + kk * 68 + ty * 8);
            const float4 xb = *(const float4*)(Xs + st * XS_ST + kk * 68 + ty * 8 + 4);
            const float4 wv = *(const float4*)(Ws + st * WS_ST + kk * 132 + tx * 4);
            ull a0 = ((const ull*)&xa)[0], a1 = ((const ull*)&xa)[1];
            ull a2 = ((const ull*)&xb)[0], a3 = ((const ull*)&xb)[1];
            ull w0 = pack2(wv.x, wv.x), w1 = pack2(wv.y, wv.y);
            ull w2 = pack2(wv.z, wv.z), w3 = pack2(wv.w, wv.w);
            fma2(acc[0][0], a0, w0); fma2(acc[0][1], a0, w1);
            fma2(acc[0][2], a0, w2); fma2(acc[0][3], a0, w3);
            fma2(acc[1][0], a1, w0); fma2(acc[1][1], a1, w1);
            fma2(acc[1][2], a1, w2); fma2(acc[1][3], a1, w3);
            fma2(acc[2][0], a2, w0); fma2(acc[2][1], a2, w1);
            fma2(acc[2][2], a2, w2); fma2(acc[2][3], a2, w3);
            fma2(acc[3][0], a3, w0); fma2(acc[3][1], a3, w1);
            fma2(acc[3][2], a3, w2); fma2(acc[3][3], a3, w3);
        }
        __syncthreads();
    }
}

// ---------------------------------------------------------------
__global__ void k_sort(const int* __restrict__ clen, const int* __restrict__ caps,
                       float* __restrict__ out) {
    int i = threadIdx.x;
    __shared__ int len[NB];
    if (i == 0) atomicExch(&g_ptick, 0u);
    if (i < NB) len[i] = clen[i];
    __syncthreads();
    if (i < NB) {
        int li = len[i], r = 0;
        for (int j = 0; j < NB; j++) {
            int lj = len[j];
            if (lj > li || (lj == li && j < i)) r++;
        }
        g_order[r] = i;
    }
    __syncthreads();
    if (i < NB) {
        int src = g_order[i];
        int dl = len[src] - 1;
        g_declen[i] = dl;
        out[OUT_DECLEN + i] = (float)dl;
        out[OUT_ORDER + i] = (float)src;
        for (int t = 0; t < NL; t++)
            out[OUT_CAPS + i * NL + t] = (float)caps[src * NL + t];
    }
}

__global__ void k_prep(const int* __restrict__ caps, const float* __restrict__ embW,
                       const float* __restrict__ enc) {
    const int bx = blockIdx.x, tid = threadIdx.x;
    if (bx < 512) {
        int b = bx >> 3;
        int e = (bx & 7) * 256 + tid;
        const float* base = enc + (size_t)g_order[b] * NP * NE + e;
        float s = 0.f;
#pragma unroll 7
        for (int p = 0; p < NP; p++) s += base[(size_t)p * NE];
        g_mean[b * NE + e] = s * (1.0f / NP);
    } else {
        int idx = bx - 512;
        int tt = idx >> 6, b = idx & 63;
        int cap = caps[g_order[b] * NL + tt];
        for (int i = tid; i < NEMB; i += 256)
            g_embT[tt][b][i] = embW[(size_t)cap * NEMB + i];
    }
}

// ---- prologue tiles (256 threads each) ----
__device__ void init_tile(int tile, const float* HW, const float* CW,
                          const float* Hb, const float* Cb, float* dyn, int tid) {
    __shared__ int lastf;
    float* Xs = dyn;
    float* Ws = dyn + 2 * XS_ST;
    const int tx = tid & 31, ty = tid >> 5;
    const int j0 = (tile & 7) * 128, ks = tile >> 3;
    const float* W = (j0 < 512) ? (HW + j0) : (CW + j0 - 512);
    ull acc[4][4] = {};
    gemm_acc<true, 16>(g_mean + ks * 512, NE, W + (size_t)ks * 512 * ND, ND, 128,
                       acc, Xs, Ws, tid);
#pragma unroll
    for (int p = 0; p < 4; p++) {
        int b0r = ty * 8 + 2 * p;
        float4 lov, hiv;
        unpack2(acc[p][0], lov.x, hiv.x); unpack2(acc[p][1], lov.y, hiv.y);
        unpack2(acc[p][2], lov.z, hiv.z); unpack2(acc[p][3], lov.w, hiv.w);
        *(float4*)&g_initp[ks][b0r * 1024 + j0 + tx * 4] = lov;
        *(float4*)&g_initp[ks][(b0r + 1) * 1024 + j0 + tx * 4] = hiv;
    }
    __threadfence();
    __syncthreads();
    if (tid == 0) lastf = (atomicAdd(&g_icnt, 1u) == 31);
    __syncthreads();
    if (lastf) {
        __threadfence();
        for (int i = tid; i < NB * 1024; i += 256) {
            int b = i >> 10, j = i & 1023;
            float s = g_initp[0][i] + g_initp[1][i] + g_initp[2][i] + g_initp[3][i];
            if (j < 512) g_h[0][b * ND + j] = s + Hb[j];
            else         g_c[b * ND + j - 512] = s + Cb[j - 512];
        }
        if (tid == 0) atomicExch(&g_icnt, 0u);
    }
}

__device__ void embg_tile(int tile, const float* Wih, const float* bih,
                          const float* bhh, float* dyn, int tid) {
    float* Xs = dyn;
    float* Ws = dyn + 2 * XS_ST;
    const int tx = tid & 31, ty = tid >> 5;
    const int t = tile >> 4;
    const int j0 = (tile & 15) * 128;
    ull acc[4][4] = {};
    gemm_acc<false, 16>(&g_embT[t][0][0], NEMB, Wih + (size_t)j0 * NX, NX, 128,
                        acc, Xs, Ws, tid);
#pragma unroll
    for (int p = 0; p < 4; p++) {
        int b0r = ty * 8 + 2 * p;
        const float4 b1 = *(const float4*)&bih[j0 + tx * 4];
        const float4 b2 = *(const float4*)&bhh[j0 + tx * 4];
        float4 lov, hiv;
        unpack2(acc[p][0], lov.x, hiv.x); unpack2(acc[p][1], lov.y, hiv.y);
        unpack2(acc[p][2], lov.z, hiv.z); unpack2(acc[p][3], lov.w, hiv.w);
        lov.x += b1.x + b2.x; lov.y += b1.y + b2.y; lov.z += b1.z + b2.z; lov.w += b1.w + b2.w;
        hiv.x += b1.x + b2.x; hiv.y += b1.y + b2.y; hiv.z += b1.z + b2.z; hiv.w += b1.w + b2.w;
        *(float4*)&g_embg[t][b0r * (4 * ND) + j0 + tx * 4] = lov;
        *(float4*)&g_embg[t][(b0r + 1) * (4 * ND) + j0 + tx * 4] = hiv;
    }
}

#define AXS_ST 4224
__device__ void att1_tile(int tile, const float* enc, const float* W,
                          const float* bias, float* dyn, int tid) {
    __shared__ int rowBase[128];
    float* Xs = dyn;
    float* Ws = dyn + 2 * AXS_ST;
    const int bn = tile & 3, bm = tile >> 2;
    const int row0 = bm * 128;
    if (tid < 128) {
        int m = row0 + tid;
        rowBase[tid] = g_order[m / NP] * NP + (m % NP);
    }
    __syncthreads();
    const int tx = tid & 31, ty = tid >> 5;
    ull acc[8][4] = {};
    auto stage = [&](int k0, int st) {
#pragma unroll
        for (int i = 0; i < 16; i++) {
            int idx = (i << 8) + tid;
            int k = idx & 31, m = idx >> 5;
            cpa4(&Xs[st * AXS_ST + k * 132 + m], enc + (size_t)rowBase[m] * NE + k0 + k);
        }
#pragma unroll
        for (int i = 0; i < 16; i++) {
            int idx = (i << 8) + tid;
            int j = idx & 127, k = idx >> 7;
            cpa4(&Ws[st * AXS_ST + k * 132 + j], W + (size_t)(k0 + k) * NA + bn * 128 + j);
        }
        CP_COMMIT;
    };
    stage(0, 0);
    for (int c = 0; c < 64; c++) {
        int st = c & 1;
        if (c < 63) { stage((c + 1) << 5, st ^ 1); CP_WAIT1; }
        else        { CP_WAIT0; }
        __syncthreads();
#pragma unroll
        for (int kk = 0; kk < 32; kk++) {
            const float* xrow = Xs + st * AXS_ST + kk * 132 + ty * 16;
            const float4 x0 = *(const float4*)(xrow);
            const float4 x1 = *(const float4*)(xrow + 4);
            const float4 x2 = *(const float4*)(xrow + 8);
            const float4 x3 = *(const float4*)(xrow + 12);
            const float4 wv = *(const float4*)(Ws + st * AXS_ST + kk * 132 + tx * 4);
            ull a[8];
            a[0] = ((const ull*)&x0)[0]; a[1] = ((const ull*)&x0)[1];
            a[2] = ((const ull*)&x1)[0]; a[3] = ((const ull*)&x1)[1];
            a[4] = ((const ull*)&x2)[0]; a[5] = ((const ull*)&x2)[1];
            a[6] = ((const ull*)&x3)[0]; a[7] = ((const ull*)&x3)[1];
            ull w0 = pack2(wv.x, wv.x), w1 = pack2(wv.y, wv.y);
            ull w2 = pack2(wv.z, wv.z), w3 = pack2(wv.w, wv.w);
#pragma unroll
            for (int p = 0; p < 8; p++) {
                fma2(acc[p][0], a[p], w0); fma2(acc[p][1], a[p], w1);
                fma2(acc[p][2], a[p], w2); fma2(acc[p][3], a[p], w3);
            }
        }
        __syncthreads();
    }
    const float4 bv = *(const float4*)&bias[bn * 128 + tx * 4];
#pragma unroll
    for (int p = 0; p < 8; p++) {
        float4 lov, hiv;
        unpack2(acc[p][0], lov.x, hiv.x); unpack2(acc[p][1], lov.y, hiv.y);
        unpack2(acc[p][2], lov.z, hiv.z); unpack2(acc[p][3], lov.w, hiv.w);
        lov.x += bv.x; lov.y += bv.y; lov.z += bv.z; lov.w += bv.w;
        hiv.x += bv.x; hiv.y += bv.y; hiv.z += bv.z; hiv.w += bv.w;
        size_t m0 = row0 + ty * 16 + 2 * p;
        *(float4*)&g_att1[m0 * NA + bn * 128 + tx * 4] = lov;
        *(float4*)&g_att1[(m0 + 1) * NA + bn * 128 + tx * 4] = hiv;
    }
}

// prologue pool: tickets 0-31 init, 32-847 embg, 848-1239 att1
__global__ __launch_bounds__(256) void k_pro(
        const float* __restrict__ enc,
        const float* __restrict__ attEncW, const float* __restrict__ attEncB,
        const float* __restrict__ Wih, const float* __restrict__ bih,
        const float* __restrict__ bhh,
        const float* __restrict__ iHW, const float* __restrict__ iCW,
        const float* __restrict__ iHb, const float* __restrict__ iCb) {
    extern __shared__ float dyn[];
    __shared__ int stk;
    const int tid = threadIdx.x;
    while (true) {
        __syncthreads();
        if (tid == 0) stk = (int)atomicAdd(&g_ptick, 1u);
        __syncthreads();
        int tk = stk;
        if (tk >= 1240) break;
        if (tk < 32)       init_tile(tk, iHW, iCW, iHb, iCb, dyn, tid);
        else if (tk < 848) embg_tile(tk - 32, Wih, bih, bhh, dyn, tid);
        else               att1_tile(tk - 848, enc, attEncW, attEncB, dyn, tid);
    }
}

// ---------------------------------------------------------------
// fused alpha + awe (512 threads, one tile per b) — R11 version
// ---------------------------------------------------------------
__device__ void alpha_awe(int b, int t, const float* __restrict__ fullw,
                          const float* __restrict__ fullb, const float* __restrict__ enc,
                          float* __restrict__ out, const int* sD, const int* sO) {
    __shared__ float att2s[NA];
    __shared__ float ws[NA];
    __shared__ float ev[NP];
    __shared__ float al[NP + 2];
    __shared__ float red[16];
    __shared__ float smax, ssum;
    const int tid = threadIdx.x, warp = tid >> 5, lane = tid & 31;
    float* aout = out + OUT_ALPHA + ((size_t)b * NT + t) * NP;
    if (t >= sD[b]) {
        if (tid < NP) aout[tid] = 0.f;
        return;
    }
    att2s[tid] = g_att2p[0][b * NA + tid] + g_att2p[1][b * NA + tid];
    ws[tid] = fullw[tid];
    __syncthreads();
    const float fb = fullb[0];
    for (int p = warp; p < NP; p += 16) {
        const float* a1 = g_att1 + ((size_t)(b * NP + p)) * NA;
        float s = 0.f;
#pragma unroll 4
        for (int a = lane; a < NA; a += 32) {
            float v = a1[a] + att2s[a];
            s += fmaxf(v, 0.f) * ws[a];
        }
#pragma unroll
        for (int o = 16; o; o >>= 1) s += __shfl_xor_sync(0xffffffffu, s, o);
        if (lane == 0) ev[p] = s + fb;
    }
    __syncthreads();
    float v = (tid < NP) ? ev[tid] : -3.0e38f;
    float m = v;
#pragma unroll
    for (int o = 16; o; o >>= 1) m = fmaxf(m, __shfl_xor_sync(0xffffffffu, m, o));
    if (lane == 0) red[warp] = m;
    __syncthreads();
    if (tid == 0) { float mm = red[0]; for (int i = 1; i < 16; i++) mm = fmaxf(mm, red[i]); smax = mm; }
    __syncthreads();
    float ex = (tid < NP) ? expf(v - smax) : 0.f;
    float s2 = ex;
#pragma unroll
    for (int o = 16; o; o >>= 1) s2 += __shfl_xor_sync(0xffffffffu, s2, o);
    if (lane == 0) red[warp] = s2;
    __syncthreads();
    if (tid == 0) { float ss = 0.f; for (int i = 0; i < 16; i++) ss += red[i]; ssum = ss; }
    __syncthreads();
    if (tid < NP) {
        float a = ex / ssum;
        al[tid] = a;
        aout[tid] = a;
    }
    if (tid >= NP && tid < NP + 2) al[tid] = 0.f;
    __syncthreads();
    const int e0 = tid * 4;
    const float* eb = enc + (size_t)sO[b] * NP * NE + e0;
    float4 aw = {0.f, 0.f, 0.f, 0.f};
    for (int p = 0; p < NP; p += 2) {
        float a0 = al[p], a1 = al[p + 1];
        const float4 r0 = *(const float4*)(eb + (size_t)p * NE);
        const float4 r1 = *(const float4*)(eb + (size_t)(p + 1) * NE);
        aw.x += a0 * r0.x + a1 * r1.x; aw.y += a0 * r0.y + a1 * r1.y;
        aw.z += a0 * r0.z + a1 * r1.z; aw.w += a0 * r0.w + a1 * r1.w;
    }
    const float4 gp0 = *(const float4*)&g_gatep[0][b * NE + e0];
    const float4 gp1 = *(const float4*)&g_gatep[1][b * NE + e0];
    float4 o0;
    o0.x = aw.x * sigf(gp0.x + gp1.x);
    o0.y = aw.y * sigf(gp0.y + gp1.y);
    o0.z = aw.z * sigf(gp0.z + gp1.z);
    o0.w = aw.w * sigf(gp0.w + gp1.w);
    *(float4*)&g_awe[b * NE + e0] = o0;
}

// ---------------------------------------------------------------
// Persistent loop (R11 best config): 148 x 512, 4 windows / step.
// ---------------------------------------------------------------
__global__ __launch_bounds__(512) void k_loop(
        const float* __restrict__ enc,
        const float* __restrict__ attW, const float* __restrict__ attb,
        const float* __restrict__ fbW,  const float* __restrict__ fbb,
        const float* __restrict__ fullw, const float* __restrict__ fullb,
        const float* __restrict__ Wih,  const float* __restrict__ Whh,
        const float* __restrict__ fcW,  const float* __restrict__ fcb,
        float* __restrict__ out) {
    extern __shared__ float dyn[];
    float* Xs = dyn;
    float* Ws = dyn + 2 * XS_ST;
    __shared__ int sD[NB], sO[NB];
    const int bid = blockIdx.x, tid = threadIdx.x;
    const int tx = tid & 63, ty = tid >> 6;
    unsigned gen = g_gen;
    if (tid < NB) { sD[tid] = g_declen[tid]; sO[tid] = g_order[tid]; }
    __syncthreads();

    for (int t = 0; t <= NT; t++) {
        const float* h = g_h[t & 1];
        const bool wact = (t < sD[ty * 8]);
        ull fA[4] = {}, fB[4] = {};
        const bool isfc = (bid >= 40 && bid < 119);
        const int fj0 = (bid - 40) * 128;
        const int fvw = (NV - fj0 > 128) ? 128 : (NV - fj0);
        const bool fcact = isfc && (t >= 1);
        const bool fwact = (t - 1 < sD[ty * 8]);

        // ---- W1 ----
        if (t < NT && bid < 8) {
            int jt = bid >> 1, ks = bid & 1, j0 = jt * 128;
            ull aA[4] = {}, aB[4] = {};
            run_kmajor<8>(h, ND, attW + j0, NA, 128, ks * 256, wact, aA, aB, Xs, Ws, tid);
            if (wact) {
                float bvA = (ks == 0) ? attb[j0 + tx] : 0.f;
                float bvB = (ks == 0) ? attb[j0 + 64 + tx] : 0.f;
#pragma unroll
                for (int p = 0; p < 4; p++) {
                    int bA = ty * 8 + 2 * p;
                    float lo, hi;
                    unpack2(aA[p], lo, hi);
                    g_att2p[ks][bA * NA + j0 + tx] = lo + bvA;
                    g_att2p[ks][(bA + 1) * NA + j0 + tx] = hi + bvA;
                    unpack2(aB[p], lo, hi);
                    g_att2p[ks][bA * NA + j0 + 64 + tx] = lo + bvB;
                    g_att2p[ks][(bA + 1) * NA + j0 + 64 + tx] = hi + bvB;
                }
            }
        } else if (t < NT && bid < 40) {
            int idx = bid - 8;
            int jt = idx >> 1, ks = idx & 1, j0 = jt * 128;
            ull aA[4] = {}, aB[4] = {};
            run_kmajor<8>(h, ND, fbW + j0, NE, 128, ks * 256, wact, aA, aB, Xs, Ws, tid);
            if (wact) {
                float bvA = (ks == 0) ? fbb[j0 + tx] : 0.f;
                float bvB = (ks == 0) ? fbb[j0 + 64 + tx] : 0.f;
#pragma unroll
                for (int p = 0; p < 4; p++) {
                    int bA = ty * 8 + 2 * p;
                    float lo, hi;
                    unpack2(aA[p], lo, hi);
                    g_gatep[ks][bA * NE + j0 + tx] = lo + bvA;
                    g_gatep[ks][(bA + 1) * NE + j0 + tx] = hi + bvA;
                    unpack2(aB[p], lo, hi);
                    g_gatep[ks][bA * NE + j0 + 64 + tx] = lo + bvB;
                    g_gatep[ks][(bA + 1) * NE + j0 + 64 + tx] = hi + bvB;
                }
            }
        } else if (fcact) {
            run_kmajor<8>(h, ND, fcW + fj0, NV, fvw, 0, fwact, fA, fB, Xs, Ws, tid);
        }
        gridbar(gen);

        // ---- W2: fc part2 + writeout | fused alpha+awe ----
        if (fcact) {
            run_kmajor<8>(h, ND, fcW + fj0, NV, fvw, 256, fwact, fA, fB, Xs, Ws, tid);
            int tprev = t - 1;
#pragma unroll
            for (int p = 0; p < 4; p++) {
                int bA = ty * 8 + 2 * p, bB = bA + 1;
                bool actA = tprev < sD[bA];
                bool actB = tprev < sD[bB];
                int cA = fj0 + tx, cB = fj0 + 64 + tx;
                float lo, hi;
                if (cA < NV) {
                    float bv = fcb[cA];
                    unpack2(fA[p], lo, hi);
                    out[OUT_PRED + (size_t)(bA * NT + tprev) * NV + cA] = actA ? lo + bv : 0.f;
                    out[OUT_PRED + (size_t)(bB * NT + tprev) * NV + cA] = actB ? hi + bv : 0.f;
                }
                if (cB < NV) {
                    float bv = fcb[cB];
                    unpack2(fB[p], lo, hi);
                    out[OUT_PRED + (size_t)(bA * NT + tprev) * NV + cB] = actA ? lo + bv : 0.f;
                    out[OUT_PRED + (size_t)(bB * NT + tprev) * NV + cB] = actB ? hi + bv : 0.f;
                }
            }
        } else if (t < NT) {
            int ab = (bid < 40) ? bid : ((bid >= 119 && bid < 143) ? bid - 79 : -1);
            if (ab >= 0) alpha_awe(ab, t, fullw, fullb, enc, out, sD, sO);
        }
        if (t == NT) break;
        gridbar(gen);

        // ---- W3: merged [h;awe] gates ----
        if (bid < 128) {
            int jt = bid & 15, ks = bid >> 4;
            int j0 = jt * 128;
            ull aA[4] = {}, aB[4] = {};
            run_mix<10>(h, g_awe, Whh + (size_t)j0 * ND, Wih + (size_t)j0 * NX,
                        ks * 320, wact, aA, aB, Xs, Ws, tid);
            if (wact) {
#pragma unroll
                for (int p = 0; p < 4; p++) {
                    int bA = ty * 8 + 2 * p;
                    float lo, hi;
                    unpack2(aA[p], lo, hi);
                    g_gawe[ks][bA * (4 * ND) + j0 + tx] = lo;
                    g_gawe[ks][(bA + 1) * (4 * ND) + j0 + tx] = hi;
                    unpack2(aB[p], lo, hi);
                    g_gawe[ks][bA * (4 * ND) + j0 + 64 + tx] = lo;
                    g_gawe[ks][(bA + 1) * (4 * ND) + j0 + 64 + tx] = hi;
                }
            }
        }
        gridbar(gen);

        // ---- W4: lstm ----
        if (bid < NB && t < sD[bid]) {
            const int b = bid, d = tid;
            float gv[4];
#pragma unroll
            for (int q = 0; q < 4; q++) {
                int j = q * ND + d;
                float s = g_embg[t][b * (4 * ND) + j];
#pragma unroll
                for (int ks = 0; ks < 8; ks++) s += g_gawe[ks][b * (4 * ND) + j];
                gv[q] = s;
            }
            float i_ = sigf(gv[0]);
            float f_ = sigf(gv[1]);
            float gg = tanhf(gv[2]);
            float o_ = sigf(gv[3]);
            float c = f_ * g_c[b * ND + d] + i_ * gg;
            g_c[b * ND + d] = c;
            g_h[(t & 1) ^ 1][b * ND + d] = o_ * tanhf(c);
        }
        gridbar(gen);
    }
}

// ---------------------------------------------------------------
extern "C" void kernel_launch(void* const* d_in, const int* in_sizes, int n_in,
                              void* d_out, int out_size) {
    (void)in_sizes; (void)n_in; (void)out_size;
    const float* enc     = (const float*)d_in[0];
    const int*   caps    = (const int*)d_in[1];
    const int*   clen    = (const int*)d_in[2];
    const float* embW    = (const float*)d_in[3];
    const float* attEncW = (const float*)d_in[4];
    const float* attEncB = (const float*)d_in[5];
    const float* attDecW = (const float*)d_in[6];
    const float* attDecB = (const float*)d_in[7];
    const float* fullW   = (const float*)d_in[8];
    const float* fullB   = (const float*)d_in[9];
    const float* Wih     = (const float*)d_in[10];
    const float* Whh     = (const float*)d_in[11];
    const float* bih     = (const float*)d_in[12];
    const float* bhh     = (const float*)d_in[13];
    const float* iHW     = (const float*)d_in[14];
    const float* iHb     = (const float*)d_in[15];
    const float* iCW     = (const float*)d_in[16];
    const float* iCb     = (const float*)d_in[17];
    const float* fbW     = (const float*)d_in[18];
    const float* fbb     = (const float*)d_in[19];
    const float* fcW     = (const float*)d_in[20];
    const float* fcb     = (const float*)d_in[21];
    float* out = (float*)d_out;

    const int SM_LOOP = (2 * XS_ST + 2 * WS_ST) * 4;   // 51200
    const int SM_PRO  = (4 * AXS_ST) * 4;              // 67584
    static int configured = 0;
    if (!configured) {
        cudaFuncSetAttribute(k_pro,  cudaFuncAttributeMaxDynamicSharedMemorySize, SM_PRO);
        cudaFuncSetAttribute(k_loop, cudaFuncAttributeMaxDynamicSharedMemorySize, SM_LOOP);
        configured = 1;
    }

    k_sort<<<1, 64>>>(clen, caps, out);
    k_prep<<<512 + NT * NB, 256>>>(caps, embW, enc);
    k_pro<<<NBLK, 256, SM_PRO>>>(enc, attEncW, attEncB, Wih, bih, bhh,
                                 iHW, iCW, iHb, iCb);
    k_loop<<<NBLK, 512, SM_LOOP>>>(enc, attDecW, attDecB, fbW, fbb,
                                   fullW, fullB, Wih, Whh, fcW, fcb, out);
}